// round 1
// baseline (speedup 1.0000x reference)
#include <cuda_runtime.h>
#include <cuda_bf16.h>
#include <math.h>

#define N_NODES 50000
#define E_EDGES 800000
#define DIN 256
#define DH 128
#define DOUT 64

// ---------------- scratch (static device globals; no allocation) ----------------
__device__ float g_h[(size_t)N_NODES * DH];     // pre-aggregation features
__device__ float g_a[(size_t)N_NODES * DH];     // post-layer activations
__device__ float g_dinv[N_NODES];
__device__ int   g_deg[N_NODES];
__device__ int   g_offs[N_NODES + 1];
__device__ int   g_cursor[N_NODES];
__device__ int   g_src_sorted[E_EDGES];
__device__ float g_norm_sorted[E_EDGES];

// ---------------- CSR construction ----------------
__global__ void k_zero(int n) {
    int i = blockIdx.x * blockDim.x + threadIdx.x;
    if (i < n) { g_deg[i] = 0; g_cursor[i] = 0; }
}

__global__ void k_count(const int* __restrict__ dst, int E) {
    int i = blockIdx.x * blockDim.x + threadIdx.x;
    if (i < E) atomicAdd(&g_deg[dst[i]], 1);
}

__global__ void k_dinv(int n) {
    int i = blockIdx.x * blockDim.x + threadIdx.x;
    if (i < n) g_dinv[i] = rsqrtf((float)g_deg[i] + 1.0f);
}

// single-block exclusive scan of g_deg -> g_offs (n up to 50000)
__global__ void k_scan(int n) {
    __shared__ int sums[1024];
    int t = threadIdx.x;
    int chunk = (n + 1023) / 1024;
    int start = t * chunk;
    int end = start + chunk; if (end > n) end = n;
    if (start > n) start = n;
    int s = 0;
    for (int i = start; i < end; i++) s += g_deg[i];
    sums[t] = s;
    __syncthreads();
    // inclusive Hillis-Steele
    for (int off = 1; off < 1024; off <<= 1) {
        int v = (t >= off) ? sums[t - off] : 0;
        __syncthreads();
        sums[t] += v;
        __syncthreads();
    }
    int base = (t == 0) ? 0 : sums[t - 1];
    for (int i = start; i < end; i++) { g_offs[i] = base; base += g_deg[i]; }
    if (t == 1023) g_offs[n] = sums[1023];
}

__global__ void k_fill(const int* __restrict__ src, const int* __restrict__ dst, int E) {
    int i = blockIdx.x * blockDim.x + threadIdx.x;
    if (i < E) {
        int d = dst[i];
        int s = src[i];
        int pos = g_offs[d] + atomicAdd(&g_cursor[d], 1);
        g_src_sorted[pos] = s;
        g_norm_sorted[pos] = g_dinv[s] * g_dinv[d];
    }
}

// ---------------- tiled fp32 GEMM: C[n,FOUT] = A[n,K] @ W[K,FOUT] ----------------
// BM=64, BK=32, blockDim (32,8) = 256 threads, per-thread 8 rows x (FOUT/32) cols
template <int FOUT>
__global__ void k_gemm(const float* __restrict__ A, const float* __restrict__ W,
                       float* __restrict__ C, int n, int K) {
    constexpr int BM = 64;
    constexpr int BK = 32;
    constexpr int CPT = FOUT / 32;     // cols per thread: 4 (F=128) or 2 (F=64)
    __shared__ float As[BK][BM + 1];
    __shared__ float Ws[BK][FOUT];

    const int tx = threadIdx.x;        // 0..31
    const int ty = threadIdx.y;        // 0..7
    const int tid = ty * 32 + tx;      // 0..255
    const int row0 = blockIdx.x * BM;

    float acc[8][CPT];
#pragma unroll
    for (int i = 0; i < 8; i++)
#pragma unroll
        for (int j = 0; j < CPT; j++) acc[i][j] = 0.0f;

    for (int k0 = 0; k0 < K; k0 += BK) {
        // load A tile: 64 rows x 32 k = 512 float4, 2 per thread
#pragma unroll
        for (int q = 0; q < 2; q++) {
            int idx4 = tid * 2 + q;           // 0..511
            int r = idx4 >> 3;                // tile row 0..63
            int c4 = idx4 & 7;                // float4 col 0..7
            int gr = row0 + r;
            float4 v = make_float4(0.f, 0.f, 0.f, 0.f);
            if (gr < n) v = *(const float4*)(A + (size_t)gr * K + k0 + c4 * 4);
            As[c4 * 4 + 0][r] = v.x;
            As[c4 * 4 + 1][r] = v.y;
            As[c4 * 4 + 2][r] = v.z;
            As[c4 * 4 + 3][r] = v.w;
        }
        // load W tile: BK x FOUT floats, contiguous
        constexpr int WQ = (BK * FOUT / 4) / 256;   // 4 (F=128) or 2 (F=64)
#pragma unroll
        for (int q = 0; q < WQ; q++) {
            int idx4 = tid + q * 256;
            int r = idx4 / (FOUT / 4);
            int c4 = idx4 % (FOUT / 4);
            float4 v = *(const float4*)(W + (size_t)(k0 + r) * FOUT + c4 * 4);
            *(float4*)&Ws[r][c4 * 4] = v;
        }
        __syncthreads();

#pragma unroll
        for (int k = 0; k < BK; k++) {
            float a[8], w[CPT];
#pragma unroll
            for (int i = 0; i < 8; i++) a[i] = As[k][ty * 8 + i];
#pragma unroll
            for (int j = 0; j < CPT; j++) w[j] = Ws[k][tx + 32 * j];
#pragma unroll
            for (int i = 0; i < 8; i++)
#pragma unroll
                for (int j = 0; j < CPT; j++) acc[i][j] = fmaf(a[i], w[j], acc[i][j]);
        }
        __syncthreads();
    }

#pragma unroll
    for (int i = 0; i < 8; i++) {
        int gr = row0 + ty * 8 + i;
        if (gr < n) {
#pragma unroll
            for (int j = 0; j < CPT; j++)
                C[(size_t)gr * FOUT + tx + 32 * j] = acc[i][j];
        }
    }
}

// ---------------- aggregation: one warp per node, gather from CSR ----------------
// MODE 0: out = relu(agg + b);  MODE 1 (F=64): out = log_softmax(agg + b)
template <int F, int MODE>
__global__ void k_agg(const float* __restrict__ h, const float* __restrict__ b,
                      float* __restrict__ out, int n) {
    int gw = (blockIdx.x * blockDim.x + threadIdx.x) >> 5;
    int lane = threadIdx.x & 31;
    if (gw >= n) return;
    constexpr int C = F / 32;

    float acc[C];
#pragma unroll
    for (int j = 0; j < C; j++) acc[j] = 0.0f;

    const int beg = g_offs[gw];
    const int end = g_offs[gw + 1];
    for (int e = beg; e < end; e++) {
        int s = g_src_sorted[e];
        float nm = g_norm_sorted[e];
        const float* hr = h + (size_t)s * F;
#pragma unroll
        for (int j = 0; j < C; j++)
            acc[j] = fmaf(hr[lane + 32 * j], nm, acc[j]);
    }
    // self loop: h[v] * dinv[v]^2
    {
        float di = g_dinv[gw];
        float sw = di * di;
        const float* hr = h + (size_t)gw * F;
#pragma unroll
        for (int j = 0; j < C; j++)
            acc[j] = fmaf(hr[lane + 32 * j], sw, acc[j]);
    }
#pragma unroll
    for (int j = 0; j < C; j++) acc[j] += b[lane + 32 * j];

    if (MODE == 0) {
#pragma unroll
        for (int j = 0; j < C; j++)
            out[(size_t)gw * F + lane + 32 * j] = fmaxf(acc[j], 0.0f);
    } else {
        // F = 64, C = 2: fused log_softmax across the warp
        float m = fmaxf(acc[0], acc[1]);
#pragma unroll
        for (int o = 16; o > 0; o >>= 1) m = fmaxf(m, __shfl_xor_sync(0xFFFFFFFFu, m, o));
        float se = expf(acc[0] - m) + expf(acc[1] - m);
#pragma unroll
        for (int o = 16; o > 0; o >>= 1) se += __shfl_xor_sync(0xFFFFFFFFu, se, o);
        float ls = m + logf(se);
        out[(size_t)gw * F + lane] = acc[0] - ls;
        out[(size_t)gw * F + lane + 32] = acc[1] - ls;
    }
}

// ---------------- launch ----------------
extern "C" void kernel_launch(void* const* d_in, const int* in_sizes, int n_in,
                              void* d_out, int out_size) {
    const float* x  = (const float*)d_in[0];
    const int* ei   = (const int*)d_in[1];
    const float* W0 = (const float*)d_in[2];
    const float* b0 = (const float*)d_in[3];
    const float* W1 = (const float*)d_in[4];
    const float* b1 = (const float*)d_in[5];
    const float* W2 = (const float*)d_in[6];
    const float* b2 = (const float*)d_in[7];
    float* out = (float*)d_out;

    const int N = in_sizes[0] / DIN;
    const int E = in_sizes[1] / 2;
    const int* src = ei;
    const int* dst = ei + E;

    float *h_ptr = nullptr, *a_ptr = nullptr;
    cudaGetSymbolAddress((void**)&h_ptr, g_h);
    cudaGetSymbolAddress((void**)&a_ptr, g_a);

    const int TB = 256;
    // CSR build
    k_zero<<<(N + TB - 1) / TB, TB>>>(N);
    k_count<<<(E + TB - 1) / TB, TB>>>(dst, E);
    k_dinv<<<(N + TB - 1) / TB, TB>>>(N);
    k_scan<<<1, 1024>>>(N);
    k_fill<<<(E + TB - 1) / TB, TB>>>(src, dst, E);

    const dim3 gblk(32, 8);
    const int agg_grid = (N * 32 + TB - 1) / TB;

    // layer 1: x[N,256] @ W0 -> h ; aggregate -> relu -> a
    k_gemm<DH><<<(N + 63) / 64, gblk>>>(x, W0, h_ptr, N, DIN);
    k_agg<DH, 0><<<agg_grid, TB>>>(h_ptr, b0, a_ptr, N);

    // layer 2: a[N,128] @ W1 -> h ; aggregate -> relu -> a
    k_gemm<DH><<<(N + 63) / 64, gblk>>>(a_ptr, W1, h_ptr, N, DH);
    k_agg<DH, 0><<<agg_grid, TB>>>(h_ptr, b1, a_ptr, N);

    // layer 3: a[N,128] @ W2 -> h(64 cols) ; aggregate + log_softmax -> out
    k_gemm<DOUT><<<(N + 63) / 64, gblk>>>(a_ptr, W2, h_ptr, N, DH);
    k_agg<DOUT, 1><<<agg_grid, TB>>>(h_ptr, b2, out, N);
}

// round 2
// speedup vs baseline: 1.5207x; 1.5207x over previous
#include <cuda_runtime.h>
#include <cuda_bf16.h>
#include <math.h>
#include <stdint.h>

#define N_NODES 50000
#define E_EDGES 800000
#define DIN 256
#define DH 128
#define DOUT 64
#define NB_SCAN ((N_NODES + 1023) / 1024)   // 49

// ---------------- scratch (static device globals; no allocation) ----------------
__device__ float g_h[(size_t)N_NODES * DH];     // pre-aggregation features
__device__ float g_a[(size_t)N_NODES * DH];     // post-layer activations
__device__ float g_dinv[N_NODES];
__device__ int   g_deg[N_NODES];
__device__ int   g_offs[N_NODES + 1];
__device__ int   g_cursor[N_NODES];
__device__ int2  g_edge[E_EDGES];               // .x = src, .y = float bits of norm
__device__ int   g_bsum[64];
__device__ int   g_bbase[64];

// ---------------- CSR construction ----------------
__global__ void k_zero(int n) {
    int i = blockIdx.x * blockDim.x + threadIdx.x;
    if (i < n) g_deg[i] = 0;
}

__global__ void k_count(const int* __restrict__ dst, int E) {
    int i = blockIdx.x * blockDim.x + threadIdx.x;
    if (i < E) atomicAdd(&g_deg[dst[i]], 1);
}

__global__ void k_dinv(int n) {
    int i = blockIdx.x * blockDim.x + threadIdx.x;
    if (i < n) g_dinv[i] = rsqrtf((float)g_deg[i] + 1.0f);
}

// scan level 1: each block scans 1024 elements (256 thr x 4), writes block sums
__global__ void k_scan1(int n) {
    __shared__ int wsum[8];
    const int t = threadIdx.x;
    const int lane = t & 31, w = t >> 5;
    const int base = blockIdx.x * 1024 + t * 4;

    int d0 = (base + 0 < n) ? g_deg[base + 0] : 0;
    int d1 = (base + 1 < n) ? g_deg[base + 1] : 0;
    int d2 = (base + 2 < n) ? g_deg[base + 2] : 0;
    int d3 = (base + 3 < n) ? g_deg[base + 3] : 0;
    int s0 = d0, s1 = s0 + d1, s2 = s1 + d2, s3 = s2 + d3;

    int ws = s3;
#pragma unroll
    for (int off = 1; off < 32; off <<= 1) {
        int v = __shfl_up_sync(0xFFFFFFFFu, ws, off);
        if (lane >= off) ws += v;
    }
    if (lane == 31) wsum[w] = ws;
    __syncthreads();
    if (w == 0 && lane < 8) {
        int v = wsum[lane];
#pragma unroll
        for (int off = 1; off < 8; off <<= 1) {
            int u = __shfl_up_sync(0x000000FFu, v, off);
            if (lane >= off) v += u;
        }
        wsum[lane] = v;
    }
    __syncthreads();
    int wbase = (w == 0) ? 0 : wsum[w - 1];
    int tbase = wbase + ws - s3;   // exclusive prefix for this thread's first elem
    if (base + 0 < n) g_offs[base + 0] = tbase;
    if (base + 1 < n) g_offs[base + 1] = tbase + s0;
    if (base + 2 < n) g_offs[base + 2] = tbase + s1;
    if (base + 3 < n) g_offs[base + 3] = tbase + s2;
    if (t == 255) g_bsum[blockIdx.x] = wsum[7];
}

// scan level 2: scan block sums (nb <= 64), one block of 64 threads
__global__ void k_scan2(int nb, int n) {
    __shared__ int sh[2];
    const int t = threadIdx.x;
    const int lane = t & 31, w = t >> 5;
    int v = (t < nb) ? g_bsum[t] : 0;
    int x = v;
#pragma unroll
    for (int off = 1; off < 32; off <<= 1) {
        int u = __shfl_up_sync(0xFFFFFFFFu, x, off);
        if (lane >= off) x += u;
    }
    if (lane == 31) sh[w] = x;
    __syncthreads();
    int incl = x + ((w == 1) ? sh[0] : 0);
    if (t < nb) g_bbase[t] = incl - v;
    if (t == nb - 1) g_offs[n] = incl;
}

// scan level 3: add block bases; also initialize cursor = offs
__global__ void k_scan3(int n) {
    const int b = g_bbase[blockIdx.x];
    const int i = blockIdx.x * 1024 + threadIdx.x * 4;
#pragma unroll
    for (int q = 0; q < 4; q++) {
        if (i + q < n) {
            int o = g_offs[i + q] + b;
            g_offs[i + q] = o;
            g_cursor[i + q] = o;
        }
    }
}

__global__ void k_fill(const int* __restrict__ src, const int* __restrict__ dst, int E) {
    int i = blockIdx.x * blockDim.x + threadIdx.x;
    if (i < E) {
        int d = dst[i];
        int s = src[i];
        int pos = atomicAdd(&g_cursor[d], 1);
        g_edge[pos] = make_int2(s, __float_as_int(g_dinv[s] * g_dinv[d]));
    }
}

// ---------------- TF32 tensor-core GEMM: C[n,F] = A[n,K] @ W[K,F] ----------------
__device__ __forceinline__ float f2tf32(float x) {
    uint32_t r;
    asm("cvt.rna.tf32.f32 %0, %1;" : "=r"(r) : "f"(x));
    return __uint_as_float(r);
}

__device__ __forceinline__ void mma_tf32(float c[4], const uint32_t a[4],
                                         uint32_t b0, uint32_t b1) {
    asm volatile(
        "mma.sync.aligned.m16n8k8.row.col.f32.tf32.tf32.f32 "
        "{%0,%1,%2,%3},{%4,%5,%6,%7},{%8,%9},{%0,%1,%2,%3};"
        : "+f"(c[0]), "+f"(c[1]), "+f"(c[2]), "+f"(c[3])
        : "r"(a[0]), "r"(a[1]), "r"(a[2]), "r"(a[3]), "r"(b0), "r"(b1));
}

// BM=64, BK=32, 256 threads = 8 warps in 2(m) x 4(n) grid.
// Warp tile: m32 x (F/4). m16n8k8 MMAs.
template <int K, int F>
__global__ void __launch_bounds__(256) k_gemm_tf32(const float* __restrict__ A,
                                                   const float* __restrict__ Wm,
                                                   float* __restrict__ C, int n) {
    constexpr int BM = 64, BK = 32;
    constexpr int AROW = 36;           // padded (x4 float-aligned, 2-way max conflicts)
    constexpr int WROW = F + 4;
    constexpr int WNW = F / 4;         // warp n-width: 32 (F=128) or 16 (F=64)
    constexpr int NT = WNW / 8;        // n8-tiles per warp: 4 or 2

    __shared__ float As[BM * AROW];
    __shared__ float Ws[BK * WROW];

    const int tid = threadIdx.x;
    const int lane = tid & 31;
    const int wid = tid >> 5;
    const int wm = wid >> 2;           // 0..1
    const int wn = wid & 3;            // 0..3
    const int g = lane >> 2;           // 0..7
    const int tg = lane & 3;           // 0..3
    const int row0 = blockIdx.x * BM;

    float acc[2][NT][4];
#pragma unroll
    for (int i = 0; i < 2; i++)
#pragma unroll
        for (int j = 0; j < NT; j++)
#pragma unroll
            for (int q = 0; q < 4; q++) acc[i][j][q] = 0.0f;

    for (int k0 = 0; k0 < K; k0 += BK) {
        // load A tile: 64x32 floats = 512 float4, 2 per thread
#pragma unroll
        for (int q = 0; q < 2; q++) {
            int idx4 = tid * 2 + q;
            int r = idx4 >> 3, c4 = idx4 & 7;
            int gr = row0 + r;
            float4 v = make_float4(0.f, 0.f, 0.f, 0.f);
            if (gr < n) v = *(const float4*)(A + (size_t)gr * K + k0 + c4 * 4);
            float4 t = make_float4(f2tf32(v.x), f2tf32(v.y), f2tf32(v.z), f2tf32(v.w));
            *(float4*)&As[r * AROW + c4 * 4] = t;
        }
        // load W tile: 32 x F floats
#pragma unroll
        for (int q = 0; q < (BK * F / 4) / 256; q++) {
            int idx4 = tid + q * 256;
            int r = idx4 / (F / 4), c4 = idx4 % (F / 4);
            float4 v = *(const float4*)(Wm + (size_t)(k0 + r) * F + c4 * 4);
            float4 t = make_float4(f2tf32(v.x), f2tf32(v.y), f2tf32(v.z), f2tf32(v.w));
            *(float4*)&Ws[r * WROW + c4 * 4] = t;
        }
        __syncthreads();

#pragma unroll
        for (int kk = 0; kk < BK; kk += 8) {
            uint32_t af[2][4];
#pragma unroll
            for (int i = 0; i < 2; i++) {
                int mb = wm * 32 + i * 16;
                af[i][0] = __float_as_uint(As[(mb + g) * AROW + kk + tg]);
                af[i][1] = __float_as_uint(As[(mb + g + 8) * AROW + kk + tg]);
                af[i][2] = __float_as_uint(As[(mb + g) * AROW + kk + tg + 4]);
                af[i][3] = __float_as_uint(As[(mb + g + 8) * AROW + kk + tg + 4]);
            }
#pragma unroll
            for (int j = 0; j < NT; j++) {
                int nb = wn * WNW + j * 8;
                uint32_t b0 = __float_as_uint(Ws[(kk + tg) * WROW + nb + g]);
                uint32_t b1 = __float_as_uint(Ws[(kk + tg + 4) * WROW + nb + g]);
#pragma unroll
                for (int i = 0; i < 2; i++) mma_tf32(acc[i][j], af[i], b0, b1);
            }
        }
        __syncthreads();
    }

#pragma unroll
    for (int i = 0; i < 2; i++) {
        int gr0 = row0 + wm * 32 + i * 16 + g;
#pragma unroll
        for (int j = 0; j < NT; j++) {
            int col = wn * WNW + j * 8 + 2 * tg;
            if (gr0 < n)
                *(float2*)(C + (size_t)gr0 * F + col) = make_float2(acc[i][j][0], acc[i][j][1]);
            if (gr0 + 8 < n)
                *(float2*)(C + (size_t)(gr0 + 8) * F + col) = make_float2(acc[i][j][2], acc[i][j][3]);
        }
    }
}

// ---------------- aggregation: one warp per node, vectorized gather ----------------
// F=128, MODE 0: out = relu(agg + b)
__global__ void k_agg128(const float* __restrict__ h, const float* __restrict__ b,
                         float* __restrict__ out, int n) {
    int gw = (blockIdx.x * blockDim.x + threadIdx.x) >> 5;
    int lane = threadIdx.x & 31;
    if (gw >= n) return;

    float4 acc = make_float4(0.f, 0.f, 0.f, 0.f);
    const int beg = g_offs[gw];
    const int end = g_offs[gw + 1];

    int e = beg;
    int2 nx = (e < end) ? g_edge[e] : make_int2(0, 0);
    while (e < end) {
        int s = nx.x;
        float nm = __int_as_float(nx.y);
        e++;
        if (e < end) nx = g_edge[e];
        float4 v = *(const float4*)(h + (size_t)s * 128 + lane * 4);
        acc.x = fmaf(v.x, nm, acc.x);
        acc.y = fmaf(v.y, nm, acc.y);
        acc.z = fmaf(v.z, nm, acc.z);
        acc.w = fmaf(v.w, nm, acc.w);
    }
    {
        float di = g_dinv[gw];
        float sw = di * di;
        float4 v = *(const float4*)(h + (size_t)gw * 128 + lane * 4);
        acc.x = fmaf(v.x, sw, acc.x);
        acc.y = fmaf(v.y, sw, acc.y);
        acc.z = fmaf(v.z, sw, acc.z);
        acc.w = fmaf(v.w, sw, acc.w);
    }
    float4 bv = *(const float4*)(b + lane * 4);
    acc.x = fmaxf(acc.x + bv.x, 0.f);
    acc.y = fmaxf(acc.y + bv.y, 0.f);
    acc.z = fmaxf(acc.z + bv.z, 0.f);
    acc.w = fmaxf(acc.w + bv.w, 0.f);
    *(float4*)(out + (size_t)gw * 128 + lane * 4) = acc;
}

// F=64 with fused log_softmax
__global__ void k_agg64_lsm(const float* __restrict__ h, const float* __restrict__ b,
                            float* __restrict__ out, int n) {
    int gw = (blockIdx.x * blockDim.x + threadIdx.x) >> 5;
    int lane = threadIdx.x & 31;
    if (gw >= n) return;

    float2 acc = make_float2(0.f, 0.f);
    const int beg = g_offs[gw];
    const int end = g_offs[gw + 1];

    int e = beg;
    int2 nx = (e < end) ? g_edge[e] : make_int2(0, 0);
    while (e < end) {
        int s = nx.x;
        float nm = __int_as_float(nx.y);
        e++;
        if (e < end) nx = g_edge[e];
        float2 v = *(const float2*)(h + (size_t)s * 64 + lane * 2);
        acc.x = fmaf(v.x, nm, acc.x);
        acc.y = fmaf(v.y, nm, acc.y);
    }
    {
        float di = g_dinv[gw];
        float sw = di * di;
        float2 v = *(const float2*)(h + (size_t)gw * 64 + lane * 2);
        acc.x = fmaf(v.x, sw, acc.x);
        acc.y = fmaf(v.y, sw, acc.y);
    }
    float2 bv = *(const float2*)(b + lane * 2);
    acc.x += bv.x;
    acc.y += bv.y;

    float m = fmaxf(acc.x, acc.y);
#pragma unroll
    for (int o = 16; o > 0; o >>= 1) m = fmaxf(m, __shfl_xor_sync(0xFFFFFFFFu, m, o));
    float se = expf(acc.x - m) + expf(acc.y - m);
#pragma unroll
    for (int o = 16; o > 0; o >>= 1) se += __shfl_xor_sync(0xFFFFFFFFu, se, o);
    float ls = m + logf(se);
    *(float2*)(out + (size_t)gw * 64 + lane * 2) = make_float2(acc.x - ls, acc.y - ls);
}

// ---------------- launch ----------------
extern "C" void kernel_launch(void* const* d_in, const int* in_sizes, int n_in,
                              void* d_out, int out_size) {
    const float* x  = (const float*)d_in[0];
    const int* ei   = (const int*)d_in[1];
    const float* W0 = (const float*)d_in[2];
    const float* b0 = (const float*)d_in[3];
    const float* W1 = (const float*)d_in[4];
    const float* b1 = (const float*)d_in[5];
    const float* W2 = (const float*)d_in[6];
    const float* b2 = (const float*)d_in[7];
    float* out = (float*)d_out;

    const int N = in_sizes[0] / DIN;
    const int E = in_sizes[1] / 2;
    const int* src = ei;
    const int* dst = ei + E;

    float *h_ptr = nullptr, *a_ptr = nullptr;
    cudaGetSymbolAddress((void**)&h_ptr, g_h);
    cudaGetSymbolAddress((void**)&a_ptr, g_a);

    const int TB = 256;
    const int nb = (N + 1023) / 1024;

    // CSR build
    k_zero <<<(N + TB - 1) / TB, TB>>>(N);
    k_count<<<(E + TB - 1) / TB, TB>>>(dst, E);
    k_dinv <<<(N + TB - 1) / TB, TB>>>(N);
    k_scan1<<<nb, 256>>>(N);
    k_scan2<<<1, 64>>>(nb, N);
    k_scan3<<<nb, 256>>>(N);
    k_fill <<<(E + TB - 1) / TB, TB>>>(src, dst, E);

    const int gemm_grid = (N + 63) / 64;
    const int agg_grid = (N * 32 + TB - 1) / TB;

    // layer 1
    k_gemm_tf32<DIN, DH><<<gemm_grid, 256>>>(x, W0, h_ptr, N);
    k_agg128<<<agg_grid, TB>>>(h_ptr, b0, a_ptr, N);

    // layer 2
    k_gemm_tf32<DH, DH><<<gemm_grid, 256>>>(a_ptr, W1, h_ptr, N);
    k_agg128<<<agg_grid, TB>>>(h_ptr, b1, a_ptr, N);

    // layer 3 + fused log_softmax
    k_gemm_tf32<DH, DOUT><<<gemm_grid, 256>>>(a_ptr, W2, h_ptr, N);
    k_agg64_lsm<<<agg_grid, TB>>>(h_ptr, b2, out, N);
}